// round 15
// baseline (speedup 1.0000x reference)
#include <cuda_runtime.h>
#include <cstdint>

// Problem constants
#define BT   512          // batches
#define TT   4096         // timesteps
#define CH   64           // steps per chunk
#define NP   32           // step-pairs per chunk
#define NCH  (TT / CH)    // 64 chunks
#define NBLK 16           // blocks (each fully independent)
#define BPB  32           // batches per block
#define NTHR 128          // 4 warps

#define DT_F     0.001f
#define C_F      1.6970562748477140f      // sqrt(4*ETA*KAPPA) = sqrt(2.88)
#define NDTC2    (-0.00288f)              // -DT * C^2
#define KX_F     (1.0f - 0.00015f)        // 1 - 0.5*GAMMA*DT
#define KCOV_F   (1.0f - 0.0003f)         // 1 - GAMMA*DT
#define DTD_F    (0.00165f)               // DT * (GAMMA*(NBAR+0.5)+KAPPA)
#define CDT_F    (C_F * DT_F)

// smem layout (bytes):
//   dyS : float2[3][32][66] = 50688 @ 0      (dy ring of 3; row 528B, cp.async-aligned)
//   bS  : float4[2][32]     =  1024 @ 50688  (pair map B = A_o A_e)
//   ghS : float4[2][32]     =  1024 @ 51712  (pair forcing vectors g, h)
//   rcS : float2[2][32]     =   512 @ 52736  (a00_e, c*vx_e for odd-step x0)
//   oS  : float2[2][32][33] = 16896 @ 53248  (pre-update (x0e, x0o) pairs)
//   rawS: float2[3][64]     =  1536 @ 70144  (riccati raw (vx,cxp) ring)
//   finS: float4            =    16 @ 71680
#define DYS_BUF_F2  2112
#define OS_BUF_F2   1056
#define SMEM_B_OFF  50688
#define SMEM_GH_OFF 51712
#define SMEM_RC_OFF 52736
#define SMEM_OS_OFF 53248
#define SMEM_RAW    70144
#define SMEM_FIN    71680
#define SMEM_TOTAL  71696

static __device__ __forceinline__ uint32_t smem_u32(const void* p) {
    uint32_t a;
    asm("{ .reg .u64 t; cvta.to.shared.u64 t, %1; cvt.u32.u64 %0, t; }" : "=r"(a) : "l"(p));
    return a;
}
static __device__ __forceinline__ void cp_async16(uint32_t dst, const void* src) {
    asm volatile("cp.async.cg.shared.global [%0], [%1], 16;" :: "r"(dst), "l"(src));
}
#define CP_COMMIT() asm volatile("cp.async.commit_group;" ::: "memory")
#define CP_WAIT1()  asm volatile("cp.async.wait_group 1;" ::: "memory")
#define CP_WAIT0()  asm volatile("cp.async.wait_group 0;" ::: "memory")

struct SmemPtrs {
    float2* dyS; float4* bS; float4* ghS; float2* rcS;
    float2* oS;  float2* rawS; float4* finS;
};

// Whole pipeline body; wdt is a compile-time literal at the w==1 call site so
// the serial riccati chain compiles to FFMA-imm forms (rt_SMSP=1 vs 2).
static __device__ __forceinline__ void run_body(
    const SmemPtrs& S, const float wdt,
    const float* __restrict__ state0, const float2* __restrict__ dyb,
    float2* __restrict__ dyh, float* __restrict__ out,
    int lane, int wid, int blk, int b)
{
    const float nwdt  = -wdt;
    const float w2dt  = 2.0f * wdt;
    const float nw2dt = -w2dt;

    float x0 = 0.f, x1 = 0.f;                       // w0
    float vx = 0.f, vp = 0.f, cxp = 0.f;            // w1 lane0

    // w1: Riccati raw chunk q -> rawS slot q%3 (pre-update (vx,cxp) pairs)
    auto riccati_raw = [&](int q) {
        float2* rg = S.rawS + (q % 3) * CH;
#pragma unroll 16
        for (int s = 0; s < CH; ++s) {
            rg[s] = make_float2(vx, cxp);
            const float m    = fmaf(NDTC2, vx, KCOV_F);       // imm
            const float g    = fmaf(w2dt, cxp, DTD_F);        // imm (w spec)
            const float h    = fmaf(wdt, vp, nwdt * vx);      // imm, imm-mul
            const float u    = fmaf(NDTC2, cxp, nw2dt);       // imm
            const float q2   = fmaf(u, cxp, DTD_F);
            const float nvx  = fmaf(m, vx, g);
            const float ncxp = fmaf(m, cxp, h);
            vp = fmaf(KCOV_F, vp, q2);                        // imm
            vx = nvx; cxp = ncxp;
        }
    };

    // w2: derive pair-composed maps for chunk q (lane = pair index)
    auto derive = [&](int q) {
        const float4 r = *reinterpret_cast<const float4*>(&S.rawS[(q % 3) * CH + 2 * lane]);
        const float a00e = fmaf(NDTC2, r.x, KX_F);
        const float a10e = fmaf(NDTC2, r.y, nwdt);
        const float a00o = fmaf(NDTC2, r.z, KX_F);
        const float a10o = fmaf(NDTC2, r.w, nwdt);
        const float cvxe = C_F * r.x, ccxpe = C_F * r.y;
        const float cvxo = C_F * r.z, ccxpo = C_F * r.w;
        const int ob = (q & 1) * NP + lane;
        S.bS[ob]  = make_float4(fmaf(a00o, a00e, wdt * a10e),    // B00
                                fmaf(a00o, wdt,  wdt * KX_F),    // B01
                                fmaf(a10o, a00e, KX_F * a10e),   // B10
                                fmaf(a10o, wdt,  KX_F * KX_F));  // B11
        S.ghS[ob] = make_float4(fmaf(a00o, cvxe, wdt * ccxpe),   // g0
                                fmaf(a10o, cvxe, KX_F * ccxpe),  // g1
                                cvxo, ccxpo);                    // h0, h1
        S.rcS[ob] = make_float2(a00e, cvxe);                     // odd-step x0 coefs
    };

    // w2: stage dy chunk c into ring slot c%3
    auto stage = [&](int c) {
        const float2*  src = dyb + c * CH;
        const uint32_t dst = smem_u32(&S.dyS[(c % 3) * DYS_BUF_F2 + lane * 66]);
#pragma unroll
        for (int k = 0; k < CH / 2; ++k) cp_async16(dst + k * 16, src + 2 * k);
        CP_COMMIT();
    };

    // w3: cheap flush — LDS.64 + 2 imm-FMUL + STG.128 per batch
    auto flush = [&](int fc) {
        const float2* ou  = S.oS + (fc & 1) * OS_BUF_F2 + lane * 33;  // row = pair
        float2*       fb2 = dyh + (size_t)(blk * BPB) * TT + fc * CH + 2 * lane;
#pragma unroll 8
        for (int bb = 0; bb < BPB; ++bb) {
            const float2 v = ou[bb];                      // (x0e, x0o) pre-update
            *reinterpret_cast<float4*>(fb2 + (size_t)bb * TT) =
                make_float4(CDT_F * v.x, 0.f, CDT_F * v.y, 0.f);
        }
    };

    // ---------------- prologue ----------------
    if (wid == 0) {
        x0 = state0[(size_t)b * 6 + 0];
        x1 = state0[(size_t)b * 6 + 1];
    } else if (wid == 1 && lane == 0) {
        vx  = state0[2];
        vp  = state0[3];
        cxp = state0[4];
        riccati_raw(0);
        riccati_raw(1);
    } else if (wid == 2) {
        stage(0);
        stage(1);
    }
    __syncthreads();
    if (wid == 2) {
        derive(0);           // pair maps for chunk 0 (raw0 ready)
        CP_WAIT1();          // dy chunk 0 resident
    }
    __syncthreads();

    // ---------------- main loop ----------------
    for (int c = 0; c < NCH; ++c) {
        if (wid == 0) {
            // x-chain: 32 pairs, static SW pipeline (4-pair groups, two register
            // buffer SETS selected by compile-time (g&1); arrays by reference).
            const float4* bP  = S.bS  + (c & 1) * NP;
            const float4* gP  = S.ghS + (c & 1) * NP;
            const float2* rP  = S.rcS + (c & 1) * NP;
            const float4* dr4 = reinterpret_cast<const float4*>(
                                    &S.dyS[(c % 3) * DYS_BUF_F2 + lane * 66]);
            float2* op = S.oS + (c & 1) * OS_BUF_F2 + lane;

            auto xload = [&](int g, float4 (&Bv)[4], float4 (&Gv)[4],
                                    float2 (&Rv)[4], float4 (&Dv)[4]) {
#pragma unroll
                for (int i = 0; i < 4; ++i) {
                    Bv[i] = bP[4 * g + i];
                    Gv[i] = gP[4 * g + i];
                    Rv[i] = rP[4 * g + i];
                    Dv[i] = dr4[4 * g + i];
                }
            };
            auto xcomp = [&](int g, float4 (&Bv)[4], float4 (&Gv)[4],
                                    float2 (&Rv)[4], float4 (&Dv)[4]) {
#pragma unroll
                for (int i = 0; i < 4; ++i) {
                    const int p = 4 * g + i;
                    const float x0o = fmaf(Rv[i].x, x0,
                                      fmaf(wdt, x1, Rv[i].y * Dv[i].x));
                    op[p * 33] = make_float2(x0, x0o);
                    const float F0  = fmaf(Dv[i].x, Gv[i].x, Dv[i].z * Gv[i].z);
                    const float F1  = fmaf(Dv[i].x, Gv[i].y, Dv[i].z * Gv[i].w);
                    const float nx0 = fmaf(Bv[i].x, x0, fmaf(Bv[i].y, x1, F0));
                    const float nx1 = fmaf(Bv[i].z, x0, fmaf(Bv[i].w, x1, F1));
                    x0 = nx0; x1 = nx1;
                }
            };

            float4 Ba[4], Ga[4], Da[4], Bb[4], Gb[4], Db[4];
            float2 Ra[4], Rb[4];
            xload(0, Ba, Ga, Ra, Da);
#pragma unroll
            for (int g = 0; g < 8; ++g) {
                if ((g & 1) == 0) {
                    if (g < 7) xload(g + 1, Bb, Gb, Rb, Db);
                    xcomp(g, Ba, Ga, Ra, Da);
                } else {
                    if (g < 7) xload(g + 1, Ba, Ga, Ra, Da);
                    xcomp(g, Bb, Gb, Rb, Db);
                }
            }
        } else if (wid == 1) {
            if (lane == 0 && c + 2 < NCH) {
                riccati_raw(c + 2);
                if (c + 2 == NCH - 1)
                    *S.finS = make_float4(vx, vp, cxp, state0[5] + DT_F * (float)TT);
            }
        } else if (wid == 2) {
            if (c + 2 < NCH)      { stage(c + 2); CP_WAIT1(); }   // c+1 resident
            else if (c + 2 == NCH) CP_WAIT0();                    // drain last
            if (c + 1 < NCH) derive(c + 1);
        } else {  // wid == 3
            if (c >= 1) flush(c - 1);
        }
        __syncthreads();
    }

    // ---------------- epilogue ----------------
    if (wid == 3) {
        flush(NCH - 1);
    } else if (wid == 0) {
        const float4 f = *S.finS;
        float* fs = out + (size_t)b * 6;
        fs[0] = x0;
        fs[1] = x1;
        fs[2] = f.x;   // vx  = ncov[0,0]
        fs[3] = f.y;   // vp  = ncov[1,1]
        fs[4] = f.z;   // cxp = ncov[1,0]
        fs[5] = f.w;   // t
    }
}

__global__ void __launch_bounds__(NTHR, 1)
grnn_kernel(const float* __restrict__ dy,
            const float* __restrict__ state0,
            const float* __restrict__ omega_p,
            float*       __restrict__ out)
{
    extern __shared__ char sm[];
    SmemPtrs S;
    S.dyS  = reinterpret_cast<float2*>(sm);
    S.bS   = reinterpret_cast<float4*>(sm + SMEM_B_OFF);
    S.ghS  = reinterpret_cast<float4*>(sm + SMEM_GH_OFF);
    S.rcS  = reinterpret_cast<float2*>(sm + SMEM_RC_OFF);
    S.oS   = reinterpret_cast<float2*>(sm + SMEM_OS_OFF);
    S.rawS = reinterpret_cast<float2*>(sm + SMEM_RAW);
    S.finS = reinterpret_cast<float4*>(sm + SMEM_FIN);

    const int tid  = threadIdx.x;
    const int lane = tid & 31;
    const int wid  = tid >> 5;
    const int blk  = blockIdx.x;
    const int b    = blk * BPB + lane;

    const float w = omega_p[0];
    const float2* dyb = reinterpret_cast<const float2*>(dy) + (size_t)b * TT;
    float2*       dyh = reinterpret_cast<float2*>(out + 6 * BT);

    if (w == 1.0f) {
        run_body(S, DT_F, state0, dyb, dyh, out, lane, wid, blk, b);      // imm path
    } else {
        run_body(S, w * DT_F, state0, dyb, dyh, out, lane, wid, blk, b);  // generic
    }
}

extern "C" void kernel_launch(void* const* d_in, const int* in_sizes, int n_in,
                              void* d_out, int out_size)
{
    const float* dy      = (const float*)d_in[0];
    const float* state0  = (const float*)d_in[1];
    const float* omega_p = (const float*)d_in[2];
    float*       out     = (float*)d_out;
    (void)in_sizes; (void)n_in; (void)out_size;

    cudaFuncSetAttribute(grnn_kernel,
                         cudaFuncAttributeMaxDynamicSharedMemorySize, SMEM_TOTAL);
    grnn_kernel<<<NBLK, NTHR, SMEM_TOTAL>>>(dy, state0, omega_p, out);
}

// round 16
// speedup vs baseline: 1.0552x; 1.0552x over previous
#include <cuda_runtime.h>
#include <cstdint>

// Problem constants
#define BT   512          // batches
#define TT   4096         // timesteps
#define CH   128          // steps per chunk (doubled: halves barrier count)
#define NP   64           // step-pairs per chunk
#define NCH  (TT / CH)    // 32 chunks
#define NBLK 16           // blocks (each fully independent)
#define BPB  32           // batches per block
#define NTHR 128          // 4 warps

#define DT_F     0.001f
#define C_F      1.6970562748477140f      // sqrt(4*ETA*KAPPA) = sqrt(2.88)
#define NDTC2    (-0.00288f)              // -DT * C^2
#define KX_F     (1.0f - 0.00015f)        // 1 - 0.5*GAMMA*DT
#define KCOV_F   (1.0f - 0.0003f)         // 1 - GAMMA*DT
#define DTD_F    (0.00165f)               // DT * (GAMMA*(NBAR+0.5)+KAPPA)
#define CDT_F    (C_F * DT_F)

// smem layout (bytes):
//   dyS : float2[3][32][130] = 99840 @ 0       (dy ring of 3; row 1040B = 65*16)
//   bS  : float4[2][64]      =  2048 @ 99840   (pair map B = A_o A_e)
//   ghS : float4[2][64]      =  2048 @ 101888  (pair forcing vectors g, h)
//   rcS : float2[2][64]      =  1024 @ 103936  (a00_e, c*vx_e for odd-step x0)
//   oS  : float2[2][64][33]  = 33792 @ 104960  (pre-update (x0e, x0o) pairs)
//   rawS: float2[3][128]     =  3072 @ 138752  (riccati raw (vx,cxp) ring)
//   finS: float4             =    16 @ 141824
#define DYS_BUF_F2  4160                  // 32*130 float2 per buffer
#define OS_BUF_F2   2112                  // 64*33 float2 per buffer
#define SMEM_B_OFF  99840
#define SMEM_GH_OFF 101888
#define SMEM_RC_OFF 103936
#define SMEM_OS_OFF 104960
#define SMEM_RAW    138752
#define SMEM_FIN    141824
#define SMEM_TOTAL  141840

static __device__ __forceinline__ uint32_t smem_u32(const void* p) {
    uint32_t a;
    asm("{ .reg .u64 t; cvta.to.shared.u64 t, %1; cvt.u32.u64 %0, t; }" : "=r"(a) : "l"(p));
    return a;
}
static __device__ __forceinline__ void cp_async16(uint32_t dst, const void* src) {
    asm volatile("cp.async.cg.shared.global [%0], [%1], 16;" :: "r"(dst), "l"(src));
}
#define CP_COMMIT() asm volatile("cp.async.commit_group;" ::: "memory")
#define CP_WAIT1()  asm volatile("cp.async.wait_group 1;" ::: "memory")
#define CP_WAIT0()  asm volatile("cp.async.wait_group 0;" ::: "memory")

struct SmemPtrs {
    float2* dyS; float4* bS; float4* ghS; float2* rcS;
    float2* oS;  float2* rawS; float4* finS;
};

// Whole pipeline body; wdt is a compile-time literal at the w==1 call site so
// the serial riccati chain compiles to FFMA-imm forms (rt_SMSP=1 vs 2).
static __device__ __forceinline__ void run_body(
    const SmemPtrs& S, const float wdt,
    const float* __restrict__ state0, const float2* __restrict__ dyb,
    float2* __restrict__ dyh, float* __restrict__ out,
    int lane, int wid, int blk, int b)
{
    const float nwdt  = -wdt;
    const float w2dt  = 2.0f * wdt;
    const float nw2dt = -w2dt;

    float x0 = 0.f, x1 = 0.f;                       // w0
    float vx = 0.f, vp = 0.f, cxp = 0.f;            // w1 lane0

    // w1: Riccati raw chunk q -> rawS slot q%3 (pre-update (vx,cxp) pairs)
    auto riccati_raw = [&](int q) {
        float2* rg = S.rawS + (q % 3) * CH;
#pragma unroll 16
        for (int s = 0; s < CH; ++s) {
            rg[s] = make_float2(vx, cxp);
            const float m    = fmaf(NDTC2, vx, KCOV_F);       // imm
            const float g    = fmaf(w2dt, cxp, DTD_F);        // imm (w spec)
            const float h    = fmaf(wdt, vp, nwdt * vx);      // imm, imm-mul
            const float u    = fmaf(NDTC2, cxp, nw2dt);       // imm
            const float q2   = fmaf(u, cxp, DTD_F);
            const float nvx  = fmaf(m, vx, g);
            const float ncxp = fmaf(m, cxp, h);
            vp = fmaf(KCOV_F, vp, q2);                        // imm
            vx = nvx; cxp = ncxp;
        }
    };

    // w2: derive pair-composed maps for chunk q (2 pairs per lane)
    auto derive = [&](int q) {
#pragma unroll
        for (int k = 0; k < 2; ++k) {
            const int p = 2 * lane + k;
            const float4 r = *reinterpret_cast<const float4*>(
                                 &S.rawS[(q % 3) * CH + 2 * p]);
            const float a00e = fmaf(NDTC2, r.x, KX_F);
            const float a10e = fmaf(NDTC2, r.y, nwdt);
            const float a00o = fmaf(NDTC2, r.z, KX_F);
            const float a10o = fmaf(NDTC2, r.w, nwdt);
            const float cvxe = C_F * r.x, ccxpe = C_F * r.y;
            const float cvxo = C_F * r.z, ccxpo = C_F * r.w;
            const int ob = (q & 1) * NP + p;
            S.bS[ob]  = make_float4(fmaf(a00o, a00e, wdt * a10e),    // B00
                                    fmaf(a00o, wdt,  wdt * KX_F),    // B01
                                    fmaf(a10o, a00e, KX_F * a10e),   // B10
                                    fmaf(a10o, wdt,  KX_F * KX_F));  // B11
            S.ghS[ob] = make_float4(fmaf(a00o, cvxe, wdt * ccxpe),   // g0
                                    fmaf(a10o, cvxe, KX_F * ccxpe),  // g1
                                    cvxo, ccxpo);                    // h0, h1
            S.rcS[ob] = make_float2(a00e, cvxe);                     // odd-step x0
        }
    };

    // w2: stage dy chunk c into ring slot c%3
    auto stage = [&](int c) {
        const float2*  src = dyb + c * CH;
        const uint32_t dst = smem_u32(&S.dyS[(c % 3) * DYS_BUF_F2 + lane * 130]);
#pragma unroll
        for (int k = 0; k < CH / 2; ++k) cp_async16(dst + k * 16, src + 2 * k);
        CP_COMMIT();
    };

    // w3: cheap flush — LDS.64 + 2 imm-FMUL + STG.128 per (pair,batch)
    auto flush = [&](int fc) {
#pragma unroll
        for (int ph = 0; ph < 2; ++ph) {
            const int pr = lane + 32 * ph;
            const float2* ou  = S.oS + (fc & 1) * OS_BUF_F2 + pr * 33;
            float2* fb2 = dyh + (size_t)(blk * BPB) * TT + fc * CH + 2 * pr;
#pragma unroll 8
            for (int bb = 0; bb < BPB; ++bb) {
                const float2 v = ou[bb];                  // (x0e, x0o) pre-update
                *reinterpret_cast<float4*>(fb2 + (size_t)bb * TT) =
                    make_float4(CDT_F * v.x, 0.f, CDT_F * v.y, 0.f);
            }
        }
    };

    // ---------------- prologue ----------------
    if (wid == 0) {
        x0 = state0[(size_t)b * 6 + 0];
        x1 = state0[(size_t)b * 6 + 1];
    } else if (wid == 1 && lane == 0) {
        vx  = state0[2];
        vp  = state0[3];
        cxp = state0[4];
        riccati_raw(0);
        riccati_raw(1);
    } else if (wid == 2) {
        stage(0);
        stage(1);
    }
    __syncthreads();
    if (wid == 2) {
        derive(0);           // pair maps for chunk 0 (raw0 ready)
        CP_WAIT1();          // dy chunk 0 resident
    }
    __syncthreads();

    // ---------------- main loop ----------------
    for (int c = 0; c < NCH; ++c) {
        if (wid == 0) {
            // x-chain: 64 pairs, static SW pipeline (4-pair groups, two register
            // buffer SETS selected by compile-time (g&1); arrays by reference).
            const float4* bP  = S.bS  + (c & 1) * NP;
            const float4* gP  = S.ghS + (c & 1) * NP;
            const float2* rP  = S.rcS + (c & 1) * NP;
            const float4* dr4 = reinterpret_cast<const float4*>(
                                    &S.dyS[(c % 3) * DYS_BUF_F2 + lane * 130]);
            float2* op = S.oS + (c & 1) * OS_BUF_F2 + lane;

            auto xload = [&](int g, float4 (&Bv)[4], float4 (&Gv)[4],
                                    float2 (&Rv)[4], float4 (&Dv)[4]) {
#pragma unroll
                for (int i = 0; i < 4; ++i) {
                    Bv[i] = bP[4 * g + i];
                    Gv[i] = gP[4 * g + i];
                    Rv[i] = rP[4 * g + i];
                    Dv[i] = dr4[4 * g + i];
                }
            };
            auto xcomp = [&](int g, float4 (&Bv)[4], float4 (&Gv)[4],
                                    float2 (&Rv)[4], float4 (&Dv)[4]) {
#pragma unroll
                for (int i = 0; i < 4; ++i) {
                    const int p = 4 * g + i;
                    const float x0o = fmaf(Rv[i].x, x0,
                                      fmaf(wdt, x1, Rv[i].y * Dv[i].x));
                    op[p * 33] = make_float2(x0, x0o);
                    const float F0  = fmaf(Dv[i].x, Gv[i].x, Dv[i].z * Gv[i].z);
                    const float F1  = fmaf(Dv[i].x, Gv[i].y, Dv[i].z * Gv[i].w);
                    const float nx0 = fmaf(Bv[i].x, x0, fmaf(Bv[i].y, x1, F0));
                    const float nx1 = fmaf(Bv[i].z, x0, fmaf(Bv[i].w, x1, F1));
                    x0 = nx0; x1 = nx1;
                }
            };

            float4 Ba[4], Ga[4], Da[4], Bb[4], Gb[4], Db[4];
            float2 Ra[4], Rb[4];
            xload(0, Ba, Ga, Ra, Da);
#pragma unroll
            for (int g = 0; g < NP / 4; ++g) {
                if ((g & 1) == 0) {
                    if (g < NP / 4 - 1) xload(g + 1, Bb, Gb, Rb, Db);
                    xcomp(g, Ba, Ga, Ra, Da);
                } else {
                    if (g < NP / 4 - 1) xload(g + 1, Ba, Ga, Ra, Da);
                    xcomp(g, Bb, Gb, Rb, Db);
                }
            }
        } else if (wid == 1) {
            if (lane == 0 && c + 2 < NCH) {
                riccati_raw(c + 2);
                if (c + 2 == NCH - 1)
                    *S.finS = make_float4(vx, vp, cxp, state0[5] + DT_F * (float)TT);
            }
        } else if (wid == 2) {
            if (c + 2 < NCH)      { stage(c + 2); CP_WAIT1(); }   // c+1 resident
            else if (c + 2 == NCH) CP_WAIT0();                    // drain last
            if (c + 1 < NCH) derive(c + 1);
        } else {  // wid == 3
            if (c >= 1) flush(c - 1);
        }
        __syncthreads();
    }

    // ---------------- epilogue ----------------
    if (wid == 3) {
        flush(NCH - 1);
    } else if (wid == 0) {
        const float4 f = *S.finS;
        float* fs = out + (size_t)b * 6;
        fs[0] = x0;
        fs[1] = x1;
        fs[2] = f.x;   // vx  = ncov[0,0]
        fs[3] = f.y;   // vp  = ncov[1,1]
        fs[4] = f.z;   // cxp = ncov[1,0]
        fs[5] = f.w;   // t
    }
}

__global__ void __launch_bounds__(NTHR, 1)
grnn_kernel(const float* __restrict__ dy,
            const float* __restrict__ state0,
            const float* __restrict__ omega_p,
            float*       __restrict__ out)
{
    extern __shared__ char sm[];
    SmemPtrs S;
    S.dyS  = reinterpret_cast<float2*>(sm);
    S.bS   = reinterpret_cast<float4*>(sm + SMEM_B_OFF);
    S.ghS  = reinterpret_cast<float4*>(sm + SMEM_GH_OFF);
    S.rcS  = reinterpret_cast<float2*>(sm + SMEM_RC_OFF);
    S.oS   = reinterpret_cast<float2*>(sm + SMEM_OS_OFF);
    S.rawS = reinterpret_cast<float2*>(sm + SMEM_RAW);
    S.finS = reinterpret_cast<float4*>(sm + SMEM_FIN);

    const int tid  = threadIdx.x;
    const int lane = tid & 31;
    const int wid  = tid >> 5;
    const int blk  = blockIdx.x;
    const int b    = blk * BPB + lane;

    const float w = omega_p[0];
    const float2* dyb = reinterpret_cast<const float2*>(dy) + (size_t)b * TT;
    float2*       dyh = reinterpret_cast<float2*>(out + 6 * BT);

    if (w == 1.0f) {
        run_body(S, DT_F, state0, dyb, dyh, out, lane, wid, blk, b);      // imm path
    } else {
        run_body(S, w * DT_F, state0, dyb, dyh, out, lane, wid, blk, b);  // generic
    }
}

extern "C" void kernel_launch(void* const* d_in, const int* in_sizes, int n_in,
                              void* d_out, int out_size)
{
    const float* dy      = (const float*)d_in[0];
    const float* state0  = (const float*)d_in[1];
    const float* omega_p = (const float*)d_in[2];
    float*       out     = (float*)d_out;
    (void)in_sizes; (void)n_in; (void)out_size;

    cudaFuncSetAttribute(grnn_kernel,
                         cudaFuncAttributeMaxDynamicSharedMemorySize, SMEM_TOTAL);
    grnn_kernel<<<NBLK, NTHR, SMEM_TOTAL>>>(dy, state0, omega_p, out);
}